// round 8
// baseline (speedup 1.0000x reference)
#include <cuda_runtime.h>
#include <math.h>

#define B   128
#define T   128
#define E   512
#define H   384
#define FH  1536
#define Z   128
#define ZH  256
#define NSTEP 127

typedef unsigned long long ull;

// ---------------- device scratch ----------------
__device__ float g_G0[NSTEP * FH * B];     // precomputed x@Wih0^T, layout [t][j][b]
__device__ float g_h0[2][H * B];           // ping-pong, layout [feature][batch]
__device__ float g_h1[2][H * B];
__device__ int   g_act[NSTEP];
__device__ __align__(16) int g_slot[128];  // barrier arrival slots (monotonic epochs)
__device__ int   g_release;                // barrier release epoch (monotonic across replays)

// ---------------- helpers ----------------
__device__ __forceinline__ ull ffma2(ull a, ull b, ull c) {
    ull d; asm("fma.rn.f32x2 %0,%1,%2,%3;" : "=l"(d) : "l"(a), "l"(b), "l"(c)); return d;
}
__device__ __forceinline__ ull pack2(float x, float y) {
    ull r; asm("mov.b64 %0,{%1,%2};" : "=l"(r) : "f"(x), "f"(y)); return r;
}
__device__ __forceinline__ float sigf(float x) { return __fdividef(1.0f, 1.0f + __expf(-x)); }

// R3-proven gsync, split into arrive / wait. Instruction-for-instruction the
// same protocol: parallel slot arrivals + CTA0-warp0 aggregation + single
// release word + thread0 poll. Warp-gated compute may be inserted between
// arrive and wait (it must not touch data protected by THIS barrier).
__device__ __forceinline__ void bar_arrive(int epoch) {
    __threadfence();
    __syncthreads();
    if (threadIdx.x == 0) *((volatile int*)&g_slot[blockIdx.x]) = epoch;
}
__device__ __forceinline__ void bar_wait(int epoch) {
    if (blockIdx.x == 0 && threadIdx.x < 32) {
        const volatile int* sp = g_slot;
        int i0 = threadIdx.x * 4;
        for (;;) {
            int a = sp[i0], b = sp[i0 + 1], c = sp[i0 + 2], d = sp[i0 + 3];
            bool ok = (a - epoch) >= 0 && (b - epoch) >= 0 && (c - epoch) >= 0 && (d - epoch) >= 0;
            if (__all_sync(0xffffffffu, ok)) break;
        }
        if (threadIdx.x == 0) *((volatile int*)&g_release) = epoch;
    }
    if (threadIdx.x == 0) { while ((*((volatile int*)&g_release) - epoch) < 0) {} }
    __syncthreads();
}

// ---------------- sticky active flags ----------------
__global__ void act_kernel(const int* __restrict__ seq) {
    __shared__ int nz[NSTEP];
    int t = threadIdx.x;
    if (t < NSTEP) {
        int s = 0;
#pragma unroll 8
        for (int b = 0; b < B; b++) s += seq[b * T + t + 1];
        nz[t] = (s != 0);
    }
    __syncthreads();
    if (t == 0) {
        int a = 1;
        for (int i = 0; i < NSTEP; i++) { a = a && nz[i]; g_act[i] = a; }
    }
}

// ---------------- precompute G0[t][j][b], 128x128 tile, f32x2 ----------------
__global__ __launch_bounds__(256) void pre_kernel(const int* __restrict__ seq,
                                                  const float* __restrict__ embed,
                                                  const float* __restrict__ Wih0) {
    const int t  = blockIdx.y;
    const int jb = blockIdx.x * 128;
    __shared__ int   s_idx[B];
    __shared__ float s_x[32 * 128];   // [k][b]
    __shared__ float s_w[32 * 128];   // [k][j]
    const int tid = threadIdx.x;
    if (tid < B) s_idx[tid] = seq[tid * T + t + 1];
    __syncthreads();

    const int col = tid & 127;
    const int kg  = tid >> 7;
    const int jt  = (tid >> 4) * 8;
    const int bt  = (tid & 15) * 8;

    ull acc[8][4];
#pragma unroll
    for (int u = 0; u < 8; u++)
#pragma unroll
        for (int v = 0; v < 4; v++) acc[u][v] = 0ull;

    const float* xrow0 = embed + (size_t)s_idx[col] * E;
    const float* wrow0 = Wih0 + (size_t)(jb + col) * E;

    for (int kc = 0; kc < E; kc += 32) {
#pragma unroll
        for (int q = 0; q < 4; q++) {
            float4 xv = __ldg((const float4*)(xrow0 + kc + kg * 16) + q);
            float4 wv = __ldg((const float4*)(wrow0 + kc + kg * 16) + q);
            int k0 = kg * 16 + q * 4;
            s_x[(k0 + 0) * 128 + col] = xv.x; s_x[(k0 + 1) * 128 + col] = xv.y;
            s_x[(k0 + 2) * 128 + col] = xv.z; s_x[(k0 + 3) * 128 + col] = xv.w;
            s_w[(k0 + 0) * 128 + col] = wv.x; s_w[(k0 + 1) * 128 + col] = wv.y;
            s_w[(k0 + 2) * 128 + col] = wv.z; s_w[(k0 + 3) * 128 + col] = wv.w;
        }
        __syncthreads();
#pragma unroll 4
        for (int k = 0; k < 32; k++) {
            const float4* xb = (const float4*)(s_x + k * 128 + bt);
            float4 x0 = xb[0], x1 = xb[1];
            ull xp0 = pack2(x0.x, x0.y), xp1 = pack2(x0.z, x0.w);
            ull xp2 = pack2(x1.x, x1.y), xp3 = pack2(x1.z, x1.w);
            const float4* wb = (const float4*)(s_w + k * 128 + jt);
            float4 w0 = wb[0], w1 = wb[1];
            float wf[8] = {w0.x, w0.y, w0.z, w0.w, w1.x, w1.y, w1.z, w1.w};
#pragma unroll
            for (int u = 0; u < 8; u++) {
                ull wp = pack2(wf[u], wf[u]);
                acc[u][0] = ffma2(xp0, wp, acc[u][0]);
                acc[u][1] = ffma2(xp1, wp, acc[u][1]);
                acc[u][2] = ffma2(xp2, wp, acc[u][2]);
                acc[u][3] = ffma2(xp3, wp, acc[u][3]);
            }
        }
        __syncthreads();
    }
#pragma unroll
    for (int u = 0; u < 8; u++) {
        ull* dst = (ull*)(g_G0 + ((size_t)t * FH + jb + jt + u) * B + bt);
        dst[0] = acc[u][0]; dst[1] = acc[u][1]; dst[2] = acc[u][2]; dst[3] = acc[u][3];
    }
}

// ---------------- GEMM slice: one warp, 32k (pass0) on row-pair weights ----------------
__device__ __forceinline__ void slice_p0(const float* __restrict__ h0r,
                                         const float2* __restrict__ sW0p,
                                         float* __restrict__ sRedP,
                                         int w, int lane, int BOFF) {
    ull acc[12][2];
#pragma unroll
    for (int r = 0; r < 12; r++) { acc[r][0] = 0ull; acc[r][1] = 0ull; }
    const int k0 = w * 32;
    float2 nb[4];
#pragma unroll
    for (int j = 0; j < 4; j++)
        nb[j] = __ldcg((const float2*)(h0r + (k0 + j) * B + BOFF) + lane);
#pragma unroll
    for (int kk = 0; kk < 32; kk += 4) {
        float2 cb[4];
#pragma unroll
        for (int j = 0; j < 4; j++) cb[j] = nb[j];
        if (kk + 4 < 32) {
#pragma unroll
            for (int j = 0; j < 4; j++)
                nb[j] = __ldcg((const float2*)(h0r + (k0 + kk + 4 + j) * B + BOFF) + lane);
        }
#pragma unroll
        for (int j = 0; j < 4; j++) {
            ull hd0 = pack2(cb[j].x, cb[j].x);
            ull hd1 = pack2(cb[j].y, cb[j].y);
            const ulonglong2* wb = (const ulonglong2*)(sW0p + (k0 + kk + j) * 12);
#pragma unroll
            for (int q = 0; q < 6; q++) {
                ulonglong2 ww = wb[q];
                acc[2 * q][0]     = ffma2(hd0, ww.x, acc[2 * q][0]);
                acc[2 * q][1]     = ffma2(hd1, ww.x, acc[2 * q][1]);
                acc[2 * q + 1][0] = ffma2(hd0, ww.y, acc[2 * q + 1][0]);
                acc[2 * q + 1][1] = ffma2(hd1, ww.y, acc[2 * q + 1][1]);
            }
        }
    }
#pragma unroll
    for (int r = 0; r < 12; r++) {
        ulonglong2 v; v.x = acc[r][0]; v.y = acc[r][1];
        *(ulonglong2*)(sRedP + (w * 12 + r) * 128 + 4 * lane) = v;
    }
}

// one warp, 64k (pass1) on row-pair weights; src/fbase resolved by caller
__device__ __forceinline__ void slice_p1(const float* __restrict__ src, int fbase,
                                         const float2* __restrict__ sW1p,
                                         float* __restrict__ sRedP,
                                         int w, int lane, int BOFF) {
    ull acc[12][2];
#pragma unroll
    for (int r = 0; r < 12; r++) { acc[r][0] = 0ull; acc[r][1] = 0ull; }
    const int k0 = w * 64;
    float2 nb[4];
#pragma unroll
    for (int j = 0; j < 4; j++)
        nb[j] = __ldcg((const float2*)(src + (fbase + j) * B + BOFF) + lane);
#pragma unroll
    for (int kk = 0; kk < 64; kk += 4) {
        float2 cb[4];
#pragma unroll
        for (int j = 0; j < 4; j++) cb[j] = nb[j];
        if (kk + 4 < 64) {
#pragma unroll
            for (int j = 0; j < 4; j++)
                nb[j] = __ldcg((const float2*)(src + (fbase + kk + 4 + j) * B + BOFF) + lane);
        }
#pragma unroll
        for (int j = 0; j < 4; j++) {
            ull hd0 = pack2(cb[j].x, cb[j].x);
            ull hd1 = pack2(cb[j].y, cb[j].y);
            const ulonglong2* wb = (const ulonglong2*)(sW1p + (k0 + kk + j) * 12);
#pragma unroll
            for (int q = 0; q < 6; q++) {
                ulonglong2 ww = wb[q];
                acc[2 * q][0]     = ffma2(hd0, ww.x, acc[2 * q][0]);
                acc[2 * q][1]     = ffma2(hd1, ww.x, acc[2 * q][1]);
                acc[2 * q + 1][0] = ffma2(hd0, ww.y, acc[2 * q + 1][0]);
                acc[2 * q + 1][1] = ffma2(hd1, ww.y, acc[2 * q + 1][1]);
            }
        }
    }
#pragma unroll
    for (int r = 0; r < 12; r++) {
        ulonglong2 v; v.x = acc[r][0]; v.y = acc[r][1];
        *(ulonglong2*)(sRedP + (w * 12 + r) * 128 + 4 * lane) = v;
    }
}

// ---------------- persistent recurrent kernel + VAE head ----------------
// 2D tiling: 128 CTAs = 64 row-groups x 2 batch-groups; CTA owns 24 gate-rows x 64 b.
// Two barriers/step, each hiding warp-gated GEMM slices between arrive and wait.
extern __shared__ char dynsmem[];

__global__ __launch_bounds__(384, 1) void rnn_kernel(
    const float* __restrict__ Whh0, const float* __restrict__ Wih1,
    const float* __restrict__ Whh1, const float* __restrict__ eps,
    const float* __restrict__ W1,   const float* __restrict__ bias1,
    const float* __restrict__ Wmu,  const float* __restrict__ bmu,
    const float* __restrict__ Wlv,  const float* __restrict__ blv,
    float* __restrict__ out) {

    float2* sW0p = (float2*)dynsmem;                       // [384][12] row-pairs (36864 B)
    float2* sW1p = (float2*)(dynsmem + 36864);             // [768][12] row-pairs (73728 B)
    float*  sRedP = (float*)(dynsmem + 36864 + 73728);     // [12 w][12 rp][128]  (73728 B)

    const int tid  = threadIdx.x;
    const int lane = tid & 31;
    const int w    = tid >> 5;
    const int bx   = blockIdx.x;
    const int RG   = bx >> 1;
    const int BOFF = (bx & 1) * 64;

    // persistent weights: pair rows (j0, j0+1) into float2
    for (int i = tid; i < 384 * 12; i += 384) {
        int k = i / 12, rp = i % 12;
        int g = rp / 3, fp = rp % 3;
        int j0 = g * H + RG * 6 + fp * 2;
        sW0p[i] = make_float2(Whh0[j0 * H + k], Whh0[(j0 + 1) * H + k]);
    }
    for (int i = tid; i < 768 * 12; i += 384) {
        int k = i / 12, rp = i % 12;
        int g = rp / 3, fp = rp % 3;
        int j0 = g * H + RG * 6 + fp * 2;
        float a, bv;
        if (k < 384) { a = Wih1[j0 * H + k];        bv = Wih1[(j0 + 1) * H + k]; }
        else         { a = Whh1[j0 * H + k - 384];  bv = Whh1[(j0 + 1) * H + k - 384]; }
        sW1p[i] = make_float2(a, bv);
    }
    const int f_e  = tid >> 6;        // 0..5
    const int bl_e = tid & 63;        // 0..63
    const int hrow = RG * 6 + f_e;
    {
        int idx = hrow * B + BOFF + bl_e;
        g_h0[0][idx] = 0.0f;
        g_h1[0][idx] = 0.0f;
    }
    float c0r = 0.0f, c1r = 0.0f;

    const int ebase = *((volatile int*)&g_release);
    int epoch = ebase;
    // initial barrier (no hidden work: inits must be grid-visible first)
    bar_arrive(++epoch);
    bar_wait(epoch);

    int p = 0;
    // pre-loop pass0(t=0): all warps, unhidden once
    if (g_act[0]) slice_p0(g_h0[0], sW0p, sRedP, w, lane, BOFF);
    __syncthreads();

    int t;
    for (t = 0; t < NSTEP; t++) {
        if (!g_act[t]) break;
        const float* h1r = g_h1[p];
        float*       h0w = g_h0[p ^ 1];
        float*       h1w = g_h1[p ^ 1];

        // ---- G0[t] gate values (L2/DRAM; issued first, consumed below)
        float g0p[4];
#pragma unroll
        for (int g = 0; g < 4; g++)
            g0p[g] = __ldcs(g_G0 + ((size_t)t * FH + g * H + hrow) * B + BOFF + bl_e);

        // ---- epilogue 0 (pass0 partials complete in sRedP)
        {
            const int rpo = (f_e >> 1);
            const int ri  = (f_e & 1);
            const int sidx = 2 * bl_e + ri;
            float gv[4];
#pragma unroll
            for (int g = 0; g < 4; g++) {
                float s = g0p[g];
                int base = (g * 3 + rpo) * 128 + sidx;
#pragma unroll
                for (int w2 = 0; w2 < 12; w2++) s += sRedP[w2 * 12 * 128 + base];
                gv[g] = s;
            }
            float nc = sigf(gv[1]) * c0r + sigf(gv[0]) * tanhf(gv[2]);
            c0r = nc;
            __stcg(h0w + hrow * B + BOFF + bl_e, sigf(gv[3]) * tanhf(nc));
        }

        // ---- MID barrier; hidden: w6-11 pass1 slices on h1r
        //      (legal: epi1(t-1) writes ordered by END barrier of t-1)
        bar_arrive(++epoch);
        if (w >= 6 && w < 12) slice_p1(h1r, (w - 6) * 64, sW1p, sRedP, w, lane, BOFF);
        bar_wait(epoch);

        // ---- pass1a: w0-5 slices on h0w (grid-visible since mid barrier)
        if (w < 6) slice_p1(h0w, w * 64, sW1p, sRedP, w, lane, BOFF);
        __syncthreads();

        // ---- epilogue 1
        {
            const int rpo = (f_e >> 1);
            const int ri  = (f_e & 1);
            const int sidx = 2 * bl_e + ri;
            float gv[4];
#pragma unroll
            for (int g = 0; g < 4; g++) {
                float s = 0.0f;
                int base = (g * 3 + rpo) * 128 + sidx;
#pragma unroll
                for (int w2 = 0; w2 < 12; w2++) s += sRedP[w2 * 12 * 128 + base];
                gv[g] = s;
            }
            float nc = sigf(gv[1]) * c1r + sigf(gv[0]) * tanhf(gv[2]);
            c1r = nc;
            __stcg(h1w + hrow * B + BOFF + bl_e, sigf(gv[3]) * tanhf(nc));
        }

        // ---- END barrier; hidden: w6-11 pass0(t+1) slices on h0w
        //      (legal: h0w synced at mid barrier; CTA0 aggregator warp w=0 not gated)
        const bool more = (t + 1 < NSTEP) && g_act[t + 1];
        bar_arrive(++epoch);
        if (more && w >= 6 && w < 12) slice_p0(h0w, sW0p, sRedP, w, lane, BOFF);
        bar_wait(epoch);

        // ---- pass0(t+1): w0-5 slices
        if (more && w < 6) slice_p0(h0w, sW0p, sRedP, w, lane, BOFF);
        __syncthreads();

        p ^= 1;
    }

    // ---- final safety barrier (h1 already synced by last END barrier)
    bar_arrive(++epoch);
    bar_wait(epoch);

    // ---- VAE head: CTA bx handles batch row b = bx
    float* s_hb = sRedP;
    float* s_hv = sRedP + 512;
    const float* h1f = g_h1[p];
    const int b = bx;
    s_hb[tid] = __ldcg(h1f + tid * B + b);   // tid < 384 == H
    __syncthreads();
    if (tid < ZH) {
        float a = bias1[tid];
        const float* wr = W1 + tid * H;
#pragma unroll 4
        for (int k = 0; k < H; k++) a = fmaf(s_hb[k], __ldg(wr + k), a);
        s_hv[tid] = fmaxf(a, 0.0f);
    }
    __syncthreads();
    if (tid < Z) {
        float mu = bmu[tid], lv = blv[tid];
        const float* wmu = Wmu + tid * ZH;
        const float* wlv = Wlv + tid * ZH;
#pragma unroll 4
        for (int k = 0; k < ZH; k++) {
            float hk = s_hv[k];
            mu = fmaf(hk, __ldg(wmu + k), mu);
            lv = fmaf(hk, __ldg(wlv + k), lv);
        }
        float zz = mu + eps[b * Z + tid] * expf(0.5f * lv);
        out[b * Z + tid] = mu;
        out[B * Z + b * Z + tid] = lv;
        out[2 * B * Z + b * (H + Z) + H + tid] = zz;
    }
    out[2 * B * Z + b * (H + Z) + tid] = s_hb[tid];   // tid < 384 == H
}

// ---------------- launch ----------------
extern "C" void kernel_launch(void* const* d_in, const int* in_sizes, int n_in,
                              void* d_out, int out_size) {
    const int*   seq   = (const int*)d_in[0];
    const float* eps   = (const float*)d_in[1];
    const float* embed = (const float*)d_in[2];
    const float* Wih0  = (const float*)d_in[3];
    const float* Whh0  = (const float*)d_in[4];
    const float* Wih1  = (const float*)d_in[5];
    const float* Whh1  = (const float*)d_in[6];
    const float* W1    = (const float*)d_in[7];
    const float* b1    = (const float*)d_in[8];
    const float* Wmu   = (const float*)d_in[9];
    const float* bmu   = (const float*)d_in[10];
    const float* Wlv   = (const float*)d_in[11];
    const float* blv   = (const float*)d_in[12];
    float* out = (float*)d_out;

    static int smem_set = 0;
    const int dyn = 36864 + 73728 + 73728;   // 184320
    if (!smem_set) {
        cudaFuncSetAttribute(rnn_kernel, cudaFuncAttributeMaxDynamicSharedMemorySize, dyn);
        smem_set = 1;
    }

    act_kernel<<<1, 128>>>(seq);
    pre_kernel<<<dim3(12, 127), 256>>>(seq, embed, Wih0);
    rnn_kernel<<<128, 384, dyn>>>(Whh0, Wih1, Whh1, eps, W1, b1, Wmu, bmu, Wlv, blv, out);
}

// round 9
// speedup vs baseline: 1.1340x; 1.1340x over previous
#include <cuda_runtime.h>
#include <math.h>

#define B   128
#define T   128
#define E   512
#define H   384
#define FH  1536
#define Z   128
#define ZH  256
#define NSTEP 127

typedef unsigned long long ull;

// ---------------- device scratch ----------------
__device__ float g_G0[NSTEP * FH * B];     // precomputed x@Wih0^T, layout [t][j][b]
__device__ float g_h0[2][H * B];           // ping-pong, layout [feature][batch]
__device__ float g_h1[2][H * B];
__device__ int   g_act[NSTEP];             // per-step nonzero flag (rnn breaks at first 0)
__device__ __align__(16) int g_slot[128];  // barrier arrival slots (monotonic epochs)
__device__ int   g_release;                // barrier release epoch (monotonic across replays)

// ---------------- helpers ----------------
__device__ __forceinline__ ull ffma2(ull a, ull b, ull c) {
    ull d; asm("fma.rn.f32x2 %0,%1,%2,%3;" : "=l"(d) : "l"(a), "l"(b), "l"(c)); return d;
}
__device__ __forceinline__ ull pack2(float x, float y) {
    ull r; asm("mov.b64 %0,{%1,%2};" : "=l"(r) : "f"(x), "f"(y)); return r;
}
__device__ __forceinline__ float sigf(float x) { return __fdividef(1.0f, 1.0f + __expf(-x)); }

// R3-proven grid barrier (DO NOT TOUCH)
__device__ __forceinline__ void gsync(int epoch) {
    __threadfence();
    __syncthreads();
    if (threadIdx.x == 0) *((volatile int*)&g_slot[blockIdx.x]) = epoch;
    if (blockIdx.x == 0 && threadIdx.x < 32) {
        const volatile int* sp = g_slot;
        int i0 = threadIdx.x * 4;
        for (;;) {
            int a = sp[i0], b = sp[i0 + 1], c = sp[i0 + 2], d = sp[i0 + 3];
            bool ok = (a - epoch) >= 0 && (b - epoch) >= 0 && (c - epoch) >= 0 && (d - epoch) >= 0;
            if (__all_sync(0xffffffffu, ok)) break;
        }
        if (threadIdx.x == 0) *((volatile int*)&g_release) = epoch;
    }
    if (threadIdx.x == 0) { while ((*((volatile int*)&g_release) - epoch) < 0) {} }
    __syncthreads();
}

// ---------------- per-step nonzero flags (parallel; no prefix needed) ----------------
__global__ void act_kernel(const int* __restrict__ seq) {
    const int t = blockIdx.x;          // 0..126
    __shared__ int ws[4];
    int v = seq[threadIdx.x * T + t + 1];
#pragma unroll
    for (int o = 16; o > 0; o >>= 1) v += __shfl_down_sync(0xffffffffu, v, o);
    if ((threadIdx.x & 31) == 0) ws[threadIdx.x >> 5] = v;
    __syncthreads();
    if (threadIdx.x == 0)
        g_act[t] = ((ws[0] + ws[1] + ws[2] + ws[3]) != 0);
}

// ---------------- precompute G0[t][j][b], 128x128 tile, f32x2 ----------------
__global__ __launch_bounds__(256) void pre_kernel(const int* __restrict__ seq,
                                                  const float* __restrict__ embed,
                                                  const float* __restrict__ Wih0) {
    const int t  = blockIdx.y;
    const int jb = blockIdx.x * 128;
    __shared__ int   s_idx[B];
    __shared__ float s_x[32 * 128];   // [k][b]
    __shared__ float s_w[32 * 128];   // [k][j]
    const int tid = threadIdx.x;
    if (tid < B) s_idx[tid] = seq[tid * T + t + 1];
    __syncthreads();

    const int col = tid & 127;
    const int kg  = tid >> 7;
    const int jt  = (tid >> 4) * 8;
    const int bt  = (tid & 15) * 8;

    ull acc[8][4];
#pragma unroll
    for (int u = 0; u < 8; u++)
#pragma unroll
        for (int v = 0; v < 4; v++) acc[u][v] = 0ull;

    const float* xrow0 = embed + (size_t)s_idx[col] * E;
    const float* wrow0 = Wih0 + (size_t)(jb + col) * E;

    for (int kc = 0; kc < E; kc += 32) {
#pragma unroll
        for (int q = 0; q < 4; q++) {
            float4 xv = __ldg((const float4*)(xrow0 + kc + kg * 16) + q);
            float4 wv = __ldg((const float4*)(wrow0 + kc + kg * 16) + q);
            int k0 = kg * 16 + q * 4;
            s_x[(k0 + 0) * 128 + col] = xv.x; s_x[(k0 + 1) * 128 + col] = xv.y;
            s_x[(k0 + 2) * 128 + col] = xv.z; s_x[(k0 + 3) * 128 + col] = xv.w;
            s_w[(k0 + 0) * 128 + col] = wv.x; s_w[(k0 + 1) * 128 + col] = wv.y;
            s_w[(k0 + 2) * 128 + col] = wv.z; s_w[(k0 + 3) * 128 + col] = wv.w;
        }
        __syncthreads();
#pragma unroll 4
        for (int k = 0; k < 32; k++) {
            const float4* xb = (const float4*)(s_x + k * 128 + bt);
            float4 x0 = xb[0], x1 = xb[1];
            ull xp0 = pack2(x0.x, x0.y), xp1 = pack2(x0.z, x0.w);
            ull xp2 = pack2(x1.x, x1.y), xp3 = pack2(x1.z, x1.w);
            const float4* wb = (const float4*)(s_w + k * 128 + jt);
            float4 w0 = wb[0], w1 = wb[1];
            float wf[8] = {w0.x, w0.y, w0.z, w0.w, w1.x, w1.y, w1.z, w1.w};
#pragma unroll
            for (int u = 0; u < 8; u++) {
                ull wp = pack2(wf[u], wf[u]);
                acc[u][0] = ffma2(xp0, wp, acc[u][0]);
                acc[u][1] = ffma2(xp1, wp, acc[u][1]);
                acc[u][2] = ffma2(xp2, wp, acc[u][2]);
                acc[u][3] = ffma2(xp3, wp, acc[u][3]);
            }
        }
        __syncthreads();
    }
#pragma unroll
    for (int u = 0; u < 8; u++) {
        ull* dst = (ull*)(g_G0 + ((size_t)t * FH + jb + jt + u) * B + bt);
        dst[0] = acc[u][0]; dst[1] = acc[u][1]; dst[2] = acc[u][2]; dst[3] = acc[u][3];
    }
}

// ---------------- persistent recurrent kernel + VAE head ----------------
// 2D tiling: 128 CTAs = 64 row-groups x 2 batch-groups.
// CTA owns 24 gate-rows {g*H + RG*6 + f} x 64 batches. 12 warps split K.
// Row-pair f32x2 weights; h duplicated per lane; load pipeline depth = 3 groups.
extern __shared__ char dynsmem[];

__global__ __launch_bounds__(384, 1) void rnn_kernel(
    const float* __restrict__ Whh0, const float* __restrict__ Wih1,
    const float* __restrict__ Whh1, const float* __restrict__ eps,
    const float* __restrict__ W1,   const float* __restrict__ bias1,
    const float* __restrict__ Wmu,  const float* __restrict__ bmu,
    const float* __restrict__ Wlv,  const float* __restrict__ blv,
    float* __restrict__ out) {

    float2* sW0p = (float2*)dynsmem;                       // [384][12] row-pairs (36864 B)
    float2* sW1p = (float2*)(dynsmem + 36864);             // [768][12] row-pairs (73728 B)
    float*  sRedP = (float*)(dynsmem + 36864 + 73728);     // [12 w][12 rp][128]  (73728 B)

    const int tid  = threadIdx.x;
    const int lane = tid & 31;
    const int w    = tid >> 5;
    const int bx   = blockIdx.x;
    const int RG   = bx >> 1;
    const int BOFF = (bx & 1) * 64;

    // persistent weights: pair rows (j0, j0+1) into float2
    for (int i = tid; i < 384 * 12; i += 384) {
        int k = i / 12, rp = i % 12;
        int g = rp / 3, fp = rp % 3;
        int j0 = g * H + RG * 6 + fp * 2;
        sW0p[i] = make_float2(Whh0[j0 * H + k], Whh0[(j0 + 1) * H + k]);
    }
    for (int i = tid; i < 768 * 12; i += 384) {
        int k = i / 12, rp = i % 12;
        int g = rp / 3, fp = rp % 3;
        int j0 = g * H + RG * 6 + fp * 2;
        float a, bv;
        if (k < 384) { a = Wih1[j0 * H + k];        bv = Wih1[(j0 + 1) * H + k]; }
        else         { a = Whh1[j0 * H + k - 384];  bv = Whh1[(j0 + 1) * H + k - 384]; }
        sW1p[i] = make_float2(a, bv);
    }
    const int f_e  = tid >> 6;        // 0..5
    const int bl_e = tid & 63;        // 0..63
    const int hrow = RG * 6 + f_e;
    {
        int idx = hrow * B + BOFF + bl_e;
        g_h0[0][idx] = 0.0f;
        g_h1[0][idx] = 0.0f;
    }
    float c0r = 0.0f, c1r = 0.0f;

    const int ebase = *((volatile int*)&g_release);
    int epoch = ebase;
    gsync(++epoch);

    int p = 0;
    int t;
    for (t = 0; t < NSTEP; t++) {
        if (!g_act[t]) break;
        const float* h0r = g_h0[p];
        float*       h0w = g_h0[p ^ 1];
        const float* h1r = g_h1[p];
        float*       h1w = g_h1[p ^ 1];

        // ---- G0[t] prefetch (consumed in epilogue0)
        float g0p[4];
#pragma unroll
        for (int g = 0; g < 4; g++)
            g0p[g] = __ldcs(g_G0 + ((size_t)t * FH + g * H + hrow) * B + BOFF + bl_e);

        // ---- pass0: 24 rows x h0r, K=384 (32 k/warp = 8 groups), depth-3 pipeline
        {
            ull acc[12][2];
#pragma unroll
            for (int r = 0; r < 12; r++) { acc[r][0] = 0ull; acc[r][1] = 0ull; }
            const int k0 = w * 32;
            float2 buf[3][4];
#pragma unroll
            for (int gq = 0; gq < 3; gq++)
#pragma unroll
                for (int j = 0; j < 4; j++)
                    buf[gq][j] = __ldcg((const float2*)(h0r + (k0 + gq * 4 + j) * B + BOFF) + lane);
#pragma unroll
            for (int gq = 0; gq < 8; gq++) {
                const int cur = gq % 3;
                float2 cb[4];
#pragma unroll
                for (int j = 0; j < 4; j++) cb[j] = buf[cur][j];
                if (gq + 3 < 8) {
#pragma unroll
                    for (int j = 0; j < 4; j++)
                        buf[cur][j] = __ldcg((const float2*)(h0r + (k0 + (gq + 3) * 4 + j) * B + BOFF) + lane);
                }
#pragma unroll
                for (int j = 0; j < 4; j++) {
                    ull hd0 = pack2(cb[j].x, cb[j].x);
                    ull hd1 = pack2(cb[j].y, cb[j].y);
                    const ulonglong2* wb = (const ulonglong2*)(sW0p + (k0 + gq * 4 + j) * 12);
#pragma unroll
                    for (int q = 0; q < 6; q++) {
                        ulonglong2 ww = wb[q];
                        acc[2 * q][0]     = ffma2(hd0, ww.x, acc[2 * q][0]);
                        acc[2 * q][1]     = ffma2(hd1, ww.x, acc[2 * q][1]);
                        acc[2 * q + 1][0] = ffma2(hd0, ww.y, acc[2 * q + 1][0]);
                        acc[2 * q + 1][1] = ffma2(hd1, ww.y, acc[2 * q + 1][1]);
                    }
                }
            }
#pragma unroll
            for (int r = 0; r < 12; r++) {
                ulonglong2 v; v.x = acc[r][0]; v.y = acc[r][1];
                *(ulonglong2*)(sRedP + (w * 12 + r) * 128 + 4 * lane) = v;
            }
        }
        __syncthreads();
        // ---- epilogue 0
        {
            const int rpo = (f_e >> 1);
            const int ri  = (f_e & 1);
            const int sidx = 2 * bl_e + ri;
            float gv[4];
#pragma unroll
            for (int g = 0; g < 4; g++) {
                float s = g0p[g];
                int base = (g * 3 + rpo) * 128 + sidx;
#pragma unroll
                for (int w2 = 0; w2 < 12; w2++) s += sRedP[w2 * 12 * 128 + base];
                gv[g] = s;
            }
            float nc = sigf(gv[1]) * c0r + sigf(gv[0]) * tanhf(gv[2]);
            c0r = nc;
            __stcg(h0w + hrow * B + BOFF + bl_e, sigf(gv[3]) * tanhf(nc));
        }
        gsync(++epoch);

        // ---- pass1: 24 rows x [h0w | h1r], K=768 (64 k/warp = 16 groups), depth-3
        {
            ull acc[12][2];
#pragma unroll
            for (int r = 0; r < 12; r++) { acc[r][0] = 0ull; acc[r][1] = 0ull; }
            const float* src   = (w < 6) ? h0w : h1r;
            const int    fbase = (w < 6) ? w * 64 : (w - 6) * 64;
            const int    k0    = w * 64;
            float2 buf[3][4];
#pragma unroll
            for (int gq = 0; gq < 3; gq++)
#pragma unroll
                for (int j = 0; j < 4; j++)
                    buf[gq][j] = __ldcg((const float2*)(src + (fbase + gq * 4 + j) * B + BOFF) + lane);
#pragma unroll
            for (int gq = 0; gq < 16; gq++) {
                const int cur = gq % 3;
                float2 cb[4];
#pragma unroll
                for (int j = 0; j < 4; j++) cb[j] = buf[cur][j];
                if (gq + 3 < 16) {
#pragma unroll
                    for (int j = 0; j < 4; j++)
                        buf[cur][j] = __ldcg((const float2*)(src + (fbase + (gq + 3) * 4 + j) * B + BOFF) + lane);
                }
#pragma unroll
                for (int j = 0; j < 4; j++) {
                    ull hd0 = pack2(cb[j].x, cb[j].x);
                    ull hd1 = pack2(cb[j].y, cb[j].y);
                    const ulonglong2* wb = (const ulonglong2*)(sW1p + (k0 + gq * 4 + j) * 12);
#pragma unroll
                    for (int q = 0; q < 6; q++) {
                        ulonglong2 ww = wb[q];
                        acc[2 * q][0]     = ffma2(hd0, ww.x, acc[2 * q][0]);
                        acc[2 * q][1]     = ffma2(hd1, ww.x, acc[2 * q][1]);
                        acc[2 * q + 1][0] = ffma2(hd0, ww.y, acc[2 * q + 1][0]);
                        acc[2 * q + 1][1] = ffma2(hd1, ww.y, acc[2 * q + 1][1]);
                    }
                }
            }
#pragma unroll
            for (int r = 0; r < 12; r++) {
                ulonglong2 v; v.x = acc[r][0]; v.y = acc[r][1];
                *(ulonglong2*)(sRedP + (w * 12 + r) * 128 + 4 * lane) = v;
            }
        }
        __syncthreads();
        // ---- epilogue 1
        {
            const int rpo = (f_e >> 1);
            const int ri  = (f_e & 1);
            const int sidx = 2 * bl_e + ri;
            float gv[4];
#pragma unroll
            for (int g = 0; g < 4; g++) {
                float s = 0.0f;
                int base = (g * 3 + rpo) * 128 + sidx;
#pragma unroll
                for (int w2 = 0; w2 < 12; w2++) s += sRedP[w2 * 12 * 128 + base];
                gv[g] = s;
            }
            float nc = sigf(gv[1]) * c1r + sigf(gv[0]) * tanhf(gv[2]);
            c1r = nc;
            __stcg(h1w + hrow * B + BOFF + bl_e, sigf(gv[3]) * tanhf(nc));
        }
        __syncthreads();   // protect sRedP before next step's stores
        p ^= 1;
    }

    // ---- FINAL grid barrier: head reads h1 features written by ALL CTAs.
    gsync(++epoch);

    // ---- VAE head: CTA bx handles batch row b = bx
    float* s_hb = sRedP;
    float* s_hv = sRedP + 512;
    const float* h1f = g_h1[p];
    const int b = bx;
    s_hb[tid] = __ldcg(h1f + tid * B + b);   // tid < 384 == H
    __syncthreads();
    if (tid < ZH) {
        float a = bias1[tid];
        const float* wr = W1 + tid * H;
#pragma unroll 4
        for (int k = 0; k < H; k++) a = fmaf(s_hb[k], __ldg(wr + k), a);
        s_hv[tid] = fmaxf(a, 0.0f);
    }
    __syncthreads();
    if (tid < Z) {
        float mu = bmu[tid], lv = blv[tid];
        const float* wmu = Wmu + tid * ZH;
        const float* wlv = Wlv + tid * ZH;
#pragma unroll 4
        for (int k = 0; k < ZH; k++) {
            float hk = s_hv[k];
            mu = fmaf(hk, __ldg(wmu + k), mu);
            lv = fmaf(hk, __ldg(wlv + k), lv);
        }
        float zz = mu + eps[b * Z + tid] * expf(0.5f * lv);
        out[b * Z + tid] = mu;
        out[B * Z + b * Z + tid] = lv;
        out[2 * B * Z + b * (H + Z) + H + tid] = zz;
    }
    out[2 * B * Z + b * (H + Z) + tid] = s_hb[tid];   // tid < 384 == H
}

// ---------------- launch ----------------
extern "C" void kernel_launch(void* const* d_in, const int* in_sizes, int n_in,
                              void* d_out, int out_size) {
    const int*   seq   = (const int*)d_in[0];
    const float* eps   = (const float*)d_in[1];
    const float* embed = (const float*)d_in[2];
    const float* Wih0  = (const float*)d_in[3];
    const float* Whh0  = (const float*)d_in[4];
    const float* Wih1  = (const float*)d_in[5];
    const float* Whh1  = (const float*)d_in[6];
    const float* W1    = (const float*)d_in[7];
    const float* b1    = (const float*)d_in[8];
    const float* Wmu   = (const float*)d_in[9];
    const float* bmu   = (const float*)d_in[10];
    const float* Wlv   = (const float*)d_in[11];
    const float* blv   = (const float*)d_in[12];
    float* out = (float*)d_out;

    static int smem_set = 0;
    const int dyn = 36864 + 73728 + 73728;   // 184320
    if (!smem_set) {
        cudaFuncSetAttribute(rnn_kernel, cudaFuncAttributeMaxDynamicSharedMemorySize, dyn);
        smem_set = 1;
    }

    act_kernel<<<NSTEP, 128>>>(seq);
    pre_kernel<<<dim3(12, 127), 256>>>(seq, embed, Wih0);
    rnn_kernel<<<128, 384, dyn>>>(Whh0, Wih1, Whh1, eps, W1, b1, Wmu, bmu, Wlv, blv, out);
}

// round 10
// speedup vs baseline: 1.1717x; 1.0332x over previous
#include <cuda_runtime.h>
#include <math.h>

#define B   128
#define T   128
#define E   512
#define H   384
#define FH  1536
#define Z   128
#define ZH  256
#define NSTEP 127

typedef unsigned long long ull;

// ---------------- device scratch ----------------
__device__ float g_G0[NSTEP * FH * B];     // precomputed x@Wih0^T, layout [t][j][b]
__device__ float g_h0[2][H * B];           // ping-pong, layout [feature][batch]
__device__ float g_h1[2][H * B];
__device__ int   g_act[NSTEP];             // per-step nonzero flag (rnn breaks at first 0)
__device__ __align__(16) int g_slot[128];  // barrier arrival slots (monotonic epochs)
__device__ int   g_release;                // barrier release epoch (monotonic across replays)

// ---------------- helpers ----------------
__device__ __forceinline__ ull ffma2(ull a, ull b, ull c) {
    ull d; asm("fma.rn.f32x2 %0,%1,%2,%3;" : "=l"(d) : "l"(a), "l"(b), "l"(c)); return d;
}
__device__ __forceinline__ ull pack2(float x, float y) {
    ull r; asm("mov.b64 %0,{%1,%2};" : "=l"(r) : "f"(x), "f"(y)); return r;
}
// single-MUFU tanh (sm_75+)
__device__ __forceinline__ float tanhap(float x) {
    float y; asm("tanh.approx.f32 %0, %1;" : "=f"(y) : "f"(x)); return y;
}
// sigmoid via tanh: sig(x) = 0.5*tanh(x/2) + 0.5   (1 MUFU + 2 flops)
__device__ __forceinline__ float sigap(float x) {
    return fmaf(0.5f, tanhap(0.5f * x), 0.5f);
}

// R3-proven grid barrier (DO NOT TOUCH)
__device__ __forceinline__ void gsync(int epoch) {
    __threadfence();
    __syncthreads();
    if (threadIdx.x == 0) *((volatile int*)&g_slot[blockIdx.x]) = epoch;
    if (blockIdx.x == 0 && threadIdx.x < 32) {
        const volatile int* sp = g_slot;
        int i0 = threadIdx.x * 4;
        for (;;) {
            int a = sp[i0], b = sp[i0 + 1], c = sp[i0 + 2], d = sp[i0 + 3];
            bool ok = (a - epoch) >= 0 && (b - epoch) >= 0 && (c - epoch) >= 0 && (d - epoch) >= 0;
            if (__all_sync(0xffffffffu, ok)) break;
        }
        if (threadIdx.x == 0) *((volatile int*)&g_release) = epoch;
    }
    if (threadIdx.x == 0) { while ((*((volatile int*)&g_release) - epoch) < 0) {} }
    __syncthreads();
}

// ---------------- per-step nonzero flags ----------------
__global__ void act_kernel(const int* __restrict__ seq) {
    const int t = blockIdx.x;          // 0..126
    __shared__ int ws[4];
    int v = seq[threadIdx.x * T + t + 1];
#pragma unroll
    for (int o = 16; o > 0; o >>= 1) v += __shfl_down_sync(0xffffffffu, v, o);
    if ((threadIdx.x & 31) == 0) ws[threadIdx.x >> 5] = v;
    __syncthreads();
    if (threadIdx.x == 0)
        g_act[t] = ((ws[0] + ws[1] + ws[2] + ws[3]) != 0);
}

// ---------------- precompute G0[t][j][b], 128x128 tile, f32x2 ----------------
__global__ __launch_bounds__(256) void pre_kernel(const int* __restrict__ seq,
                                                  const float* __restrict__ embed,
                                                  const float* __restrict__ Wih0) {
    const int t  = blockIdx.y;
    const int jb = blockIdx.x * 128;
    __shared__ int   s_idx[B];
    __shared__ float s_x[32 * 128];   // [k][b]
    __shared__ float s_w[32 * 128];   // [k][j]
    const int tid = threadIdx.x;
    if (tid < B) s_idx[tid] = seq[tid * T + t + 1];
    __syncthreads();

    const int col = tid & 127;
    const int kg  = tid >> 7;
    const int jt  = (tid >> 4) * 8;
    const int bt  = (tid & 15) * 8;

    ull acc[8][4];
#pragma unroll
    for (int u = 0; u < 8; u++)
#pragma unroll
        for (int v = 0; v < 4; v++) acc[u][v] = 0ull;

    const float* xrow0 = embed + (size_t)s_idx[col] * E;
    const float* wrow0 = Wih0 + (size_t)(jb + col) * E;

    for (int kc = 0; kc < E; kc += 32) {
#pragma unroll
        for (int q = 0; q < 4; q++) {
            float4 xv = __ldg((const float4*)(xrow0 + kc + kg * 16) + q);
            float4 wv = __ldg((const float4*)(wrow0 + kc + kg * 16) + q);
            int k0 = kg * 16 + q * 4;
            s_x[(k0 + 0) * 128 + col] = xv.x; s_x[(k0 + 1) * 128 + col] = xv.y;
            s_x[(k0 + 2) * 128 + col] = xv.z; s_x[(k0 + 3) * 128 + col] = xv.w;
            s_w[(k0 + 0) * 128 + col] = wv.x; s_w[(k0 + 1) * 128 + col] = wv.y;
            s_w[(k0 + 2) * 128 + col] = wv.z; s_w[(k0 + 3) * 128 + col] = wv.w;
        }
        __syncthreads();
#pragma unroll 4
        for (int k = 0; k < 32; k++) {
            const float4* xb = (const float4*)(s_x + k * 128 + bt);
            float4 x0 = xb[0], x1 = xb[1];
            ull xp0 = pack2(x0.x, x0.y), xp1 = pack2(x0.z, x0.w);
            ull xp2 = pack2(x1.x, x1.y), xp3 = pack2(x1.z, x1.w);
            const float4* wb = (const float4*)(s_w + k * 128 + jt);
            float4 w0 = wb[0], w1 = wb[1];
            float wf[8] = {w0.x, w0.y, w0.z, w0.w, w1.x, w1.y, w1.z, w1.w};
#pragma unroll
            for (int u = 0; u < 8; u++) {
                ull wp = pack2(wf[u], wf[u]);
                acc[u][0] = ffma2(xp0, wp, acc[u][0]);
                acc[u][1] = ffma2(xp1, wp, acc[u][1]);
                acc[u][2] = ffma2(xp2, wp, acc[u][2]);
                acc[u][3] = ffma2(xp3, wp, acc[u][3]);
            }
        }
        __syncthreads();
    }
#pragma unroll
    for (int u = 0; u < 8; u++) {
        ull* dst = (ull*)(g_G0 + ((size_t)t * FH + jb + jt + u) * B + bt);
        dst[0] = acc[u][0]; dst[1] = acc[u][1]; dst[2] = acc[u][2]; dst[3] = acc[u][3];
    }
}

// ---------------- persistent recurrent kernel + VAE head ----------------
// 2D tiling: 128 CTAs = 64 row-groups x 2 batch-groups.
// CTA owns 24 gate-rows {g*H + RG*6 + f} x 64 batches. 12 warps split K.
// Row-pair f32x2 weights; h duplicated per lane; depth-3 load pipeline.
// Epilogue thread role: sidx = tid&127 (conflict-free LDS), rpo = tid>>7.
extern __shared__ char dynsmem[];

__global__ __launch_bounds__(384, 1) void rnn_kernel(
    const float* __restrict__ Whh0, const float* __restrict__ Wih1,
    const float* __restrict__ Whh1, const float* __restrict__ eps,
    const float* __restrict__ W1,   const float* __restrict__ bias1,
    const float* __restrict__ Wmu,  const float* __restrict__ bmu,
    const float* __restrict__ Wlv,  const float* __restrict__ blv,
    float* __restrict__ out) {

    float2* sW0p = (float2*)dynsmem;                       // [384][12] row-pairs (36864 B)
    float2* sW1p = (float2*)(dynsmem + 36864);             // [768][12] row-pairs (73728 B)
    float*  sRedP = (float*)(dynsmem + 36864 + 73728);     // [12 w][12 rp][128]  (73728 B)

    const int tid  = threadIdx.x;
    const int lane = tid & 31;
    const int w    = tid >> 5;
    const int bx   = blockIdx.x;
    const int RG   = bx >> 1;
    const int BOFF = (bx & 1) * 64;

    // persistent weights: pair rows (j0, j0+1) into float2
    for (int i = tid; i < 384 * 12; i += 384) {
        int k = i / 12, rp = i % 12;
        int g = rp / 3, fp = rp % 3;
        int j0 = g * H + RG * 6 + fp * 2;
        sW0p[i] = make_float2(Whh0[j0 * H + k], Whh0[(j0 + 1) * H + k]);
    }
    for (int i = tid; i < 768 * 12; i += 384) {
        int k = i / 12, rp = i % 12;
        int g = rp / 3, fp = rp % 3;
        int j0 = g * H + RG * 6 + fp * 2;
        float a, bv;
        if (k < 384) { a = Wih1[j0 * H + k];        bv = Wih1[(j0 + 1) * H + k]; }
        else         { a = Whh1[j0 * H + k - 384];  bv = Whh1[(j0 + 1) * H + k - 384]; }
        sW1p[i] = make_float2(a, bv);
    }
    // epilogue role: conflict-free mapping
    const int e_sidx = tid & 127;            // sRedP column (lane-consecutive)
    const int e_rpo  = tid >> 7;             // 0..2 row-pair group
    const int e_ri   = e_sidx & 1;           // row-in-pair
    const int e_bl   = e_sidx >> 1;          // 0..63 batch lane
    const int hrow   = RG * 6 + e_rpo * 2 + e_ri;
    {
        int idx = hrow * B + BOFF + e_bl;
        g_h0[0][idx] = 0.0f;
        g_h1[0][idx] = 0.0f;
    }
    float c0r = 0.0f, c1r = 0.0f;

    const int ebase = *((volatile int*)&g_release);
    int epoch = ebase;
    gsync(++epoch);

    int p = 0;
    int t;
    for (t = 0; t < NSTEP; t++) {
        if (!g_act[t]) break;
        const float* h0r = g_h0[p];
        float*       h0w = g_h0[p ^ 1];
        const float* h1r = g_h1[p];
        float*       h1w = g_h1[p ^ 1];

        // ---- G0[t] prefetch (consumed in epilogue0)
        float g0p[4];
#pragma unroll
        for (int g = 0; g < 4; g++)
            g0p[g] = __ldcs(g_G0 + ((size_t)t * FH + g * H + hrow) * B + BOFF + e_bl);

        // ---- pass0: 24 rows x h0r, K=384 (32 k/warp = 8 groups), depth-3 pipeline
        {
            ull acc[12][2];
#pragma unroll
            for (int r = 0; r < 12; r++) { acc[r][0] = 0ull; acc[r][1] = 0ull; }
            const int k0 = w * 32;
            float2 buf[3][4];
#pragma unroll
            for (int gq = 0; gq < 3; gq++)
#pragma unroll
                for (int j = 0; j < 4; j++)
                    buf[gq][j] = __ldcg((const float2*)(h0r + (k0 + gq * 4 + j) * B + BOFF) + lane);
#pragma unroll
            for (int gq = 0; gq < 8; gq++) {
                const int cur = gq % 3;
                float2 cb[4];
#pragma unroll
                for (int j = 0; j < 4; j++) cb[j] = buf[cur][j];
                if (gq + 3 < 8) {
#pragma unroll
                    for (int j = 0; j < 4; j++)
                        buf[cur][j] = __ldcg((const float2*)(h0r + (k0 + (gq + 3) * 4 + j) * B + BOFF) + lane);
                }
#pragma unroll
                for (int j = 0; j < 4; j++) {
                    ull hd0 = pack2(cb[j].x, cb[j].x);
                    ull hd1 = pack2(cb[j].y, cb[j].y);
                    const ulonglong2* wb = (const ulonglong2*)(sW0p + (k0 + gq * 4 + j) * 12);
#pragma unroll
                    for (int q = 0; q < 6; q++) {
                        ulonglong2 ww = wb[q];
                        acc[2 * q][0]     = ffma2(hd0, ww.x, acc[2 * q][0]);
                        acc[2 * q][1]     = ffma2(hd1, ww.x, acc[2 * q][1]);
                        acc[2 * q + 1][0] = ffma2(hd0, ww.y, acc[2 * q + 1][0]);
                        acc[2 * q + 1][1] = ffma2(hd1, ww.y, acc[2 * q + 1][1]);
                    }
                }
            }
#pragma unroll
            for (int r = 0; r < 12; r++) {
                ulonglong2 v; v.x = acc[r][0]; v.y = acc[r][1];
                *(ulonglong2*)(sRedP + (w * 12 + r) * 128 + 4 * lane) = v;
            }
        }
        __syncthreads();
        // ---- epilogue 0 (conflict-free LDS; MUFU tanh activations)
        {
            float gv[4];
#pragma unroll
            for (int g = 0; g < 4; g++) {
                float s = g0p[g];
                int base = (g * 3 + e_rpo) * 128 + e_sidx;
#pragma unroll
                for (int w2 = 0; w2 < 12; w2++) s += sRedP[w2 * 12 * 128 + base];
                gv[g] = s;
            }
            float nc = sigap(gv[1]) * c0r + sigap(gv[0]) * tanhap(gv[2]);
            c0r = nc;
            __stcg(h0w + hrow * B + BOFF + e_bl, sigap(gv[3]) * tanhap(nc));
        }
        gsync(++epoch);

        // ---- pass1: 24 rows x [h0w | h1r], K=768 (64 k/warp = 16 groups), depth-3
        {
            ull acc[12][2];
#pragma unroll
            for (int r = 0; r < 12; r++) { acc[r][0] = 0ull; acc[r][1] = 0ull; }
            const float* src   = (w < 6) ? h0w : h1r;
            const int    fbase = (w < 6) ? w * 64 : (w - 6) * 64;
            const int    k0    = w * 64;
            float2 buf[3][4];
#pragma unroll
            for (int gq = 0; gq < 3; gq++)
#pragma unroll
                for (int j = 0; j < 4; j++)
                    buf[gq][j] = __ldcg((const float2*)(src + (fbase + gq * 4 + j) * B + BOFF) + lane);
#pragma unroll
            for (int gq = 0; gq < 16; gq++) {
                const int cur = gq % 3;
                float2 cb[4];
#pragma unroll
                for (int j = 0; j < 4; j++) cb[j] = buf[cur][j];
                if (gq + 3 < 16) {
#pragma unroll
                    for (int j = 0; j < 4; j++)
                        buf[cur][j] = __ldcg((const float2*)(src + (fbase + (gq + 3) * 4 + j) * B + BOFF) + lane);
                }
#pragma unroll
                for (int j = 0; j < 4; j++) {
                    ull hd0 = pack2(cb[j].x, cb[j].x);
                    ull hd1 = pack2(cb[j].y, cb[j].y);
                    const ulonglong2* wb = (const ulonglong2*)(sW1p + (k0 + gq * 4 + j) * 12);
#pragma unroll
                    for (int q = 0; q < 6; q++) {
                        ulonglong2 ww = wb[q];
                        acc[2 * q][0]     = ffma2(hd0, ww.x, acc[2 * q][0]);
                        acc[2 * q][1]     = ffma2(hd1, ww.x, acc[2 * q][1]);
                        acc[2 * q + 1][0] = ffma2(hd0, ww.y, acc[2 * q + 1][0]);
                        acc[2 * q + 1][1] = ffma2(hd1, ww.y, acc[2 * q + 1][1]);
                    }
                }
            }
#pragma unroll
            for (int r = 0; r < 12; r++) {
                ulonglong2 v; v.x = acc[r][0]; v.y = acc[r][1];
                *(ulonglong2*)(sRedP + (w * 12 + r) * 128 + 4 * lane) = v;
            }
        }
        __syncthreads();
        // ---- epilogue 1
        {
            float gv[4];
#pragma unroll
            for (int g = 0; g < 4; g++) {
                float s = 0.0f;
                int base = (g * 3 + e_rpo) * 128 + e_sidx;
#pragma unroll
                for (int w2 = 0; w2 < 12; w2++) s += sRedP[w2 * 12 * 128 + base];
                gv[g] = s;
            }
            float nc = sigap(gv[1]) * c1r + sigap(gv[0]) * tanhap(gv[2]);
            c1r = nc;
            __stcg(h1w + hrow * B + BOFF + e_bl, sigap(gv[3]) * tanhap(nc));
        }
        __syncthreads();   // protect sRedP before next step's stores
        p ^= 1;
    }

    // ---- FINAL grid barrier: head reads h1 features written by ALL CTAs.
    gsync(++epoch);

    // ---- VAE head: CTA bx handles batch row b = bx
    float* s_hb = sRedP;
    float* s_hv = sRedP + 512;
    const float* h1f = g_h1[p];
    const int b = bx;
    s_hb[tid] = __ldcg(h1f + tid * B + b);   // tid < 384 == H
    __syncthreads();
    if (tid < ZH) {
        float a = bias1[tid];
        const float* wr = W1 + tid * H;
#pragma unroll 4
        for (int k = 0; k < H; k++) a = fmaf(s_hb[k], __ldg(wr + k), a);
        s_hv[tid] = fmaxf(a, 0.0f);
    }
    __syncthreads();
    if (tid < Z) {
        float mu = bmu[tid], lv = blv[tid];
        const float* wmu = Wmu + tid * ZH;
        const float* wlv = Wlv + tid * ZH;
#pragma unroll 4
        for (int k = 0; k < ZH; k++) {
            float hk = s_hv[k];
            mu = fmaf(hk, __ldg(wmu + k), mu);
            lv = fmaf(hk, __ldg(wlv + k), lv);
        }
        float zz = mu + eps[b * Z + tid] * expf(0.5f * lv);
        out[b * Z + tid] = mu;
        out[B * Z + b * Z + tid] = lv;
        out[2 * B * Z + b * (H + Z) + H + tid] = zz;
    }
    out[2 * B * Z + b * (H + Z) + tid] = s_hb[tid];   // tid < 384 == H
}

// ---------------- launch ----------------
extern "C" void kernel_launch(void* const* d_in, const int* in_sizes, int n_in,
                              void* d_out, int out_size) {
    const int*   seq   = (const int*)d_in[0];
    const float* eps   = (const float*)d_in[1];
    const float* embed = (const float*)d_in[2];
    const float* Wih0  = (const float*)d_in[3];
    const float* Whh0  = (const float*)d_in[4];
    const float* Wih1  = (const float*)d_in[5];
    const float* Whh1  = (const float*)d_in[6];
    const float* W1    = (const float*)d_in[7];
    const float* b1    = (const float*)d_in[8];
    const float* Wmu   = (const float*)d_in[9];
    const float* bmu   = (const float*)d_in[10];
    const float* Wlv   = (const float*)d_in[11];
    const float* blv   = (const float*)d_in[12];
    float* out = (float*)d_out;

    static int smem_set = 0;
    const int dyn = 36864 + 73728 + 73728;   // 184320
    if (!smem_set) {
        cudaFuncSetAttribute(rnn_kernel, cudaFuncAttributeMaxDynamicSharedMemorySize, dyn);
        smem_set = 1;
    }

    act_kernel<<<NSTEP, 128>>>(seq);
    pre_kernel<<<dim3(12, 127), 256>>>(seq, embed, Wih0);
    rnn_kernel<<<128, 384, dyn>>>(Whh0, Wih1, Whh1, eps, W1, b1, Wmu, bmu, Wlv, blv, out);
}